// round 7
// baseline (speedup 1.0000x reference)
#include <cuda_runtime.h>
#include <cuda_fp16.h>
#include <cstdint>

#define N_ROWS 32768
#define DIM    256
#define NE     8192

#define MTILE  128
#define NTILE  128
#define CHUNKS (NE / NTILE)   // 64
#define KITERS (DIM / 16)     // 16

#define NCAND  16             // 8 per n-half (two warps per row band)
#define MARGIN 0.5f

#define INDOFF  (N_ROWS * DIM)         // 2097152
#define LOSSOFF (INDOFF + N_ROWS)      // 2129920

// smem layout (bytes)
#define OFF_A    0
#define OFF_B0   65536
#define OFF_B1   131072
#define OFF_NRM  196608
#define SMEM_BYTES 229376              // 224 KB

// Scratch (device globals: allocation-free per harness rules)
__device__ float  g_embedT[(size_t)NE * DIM];   // [8192][256] fp32 codebook rows
__device__ float  g_norms[NE];                  // ||e_j||^2
__device__ __half g_a_f16[(size_t)N_ROWS * DIM];
__device__ __half g_e_f16[(size_t)NE * DIM];
__device__ int    g_cand[(size_t)N_ROWS * NCAND];
__device__ int    g_idx[N_ROWS];
__device__ float  g_partial[N_ROWS / 64];       // 512 loss partials

// ---------------------------------------------------------------------------
// PTX helpers (base-target sm_80+ only — no 'a'-suffix features)
// ---------------------------------------------------------------------------
__device__ __forceinline__ uint32_t smem_u32(const void* p) {
    uint32_t a;
    asm("{ .reg .u64 t; cvta.to.shared.u64 t, %1; cvt.u32.u64 %0, t; }"
        : "=r"(a) : "l"(p));
    return a;
}
__device__ __forceinline__ void cpasync16(uint32_t dst, const void* src) {
    asm volatile("cp.async.cg.shared.global [%0], [%1], 16;"
                 :: "r"(dst), "l"(src) : "memory");
}
#define CP_COMMIT() asm volatile("cp.async.commit_group;" ::: "memory")
#define CP_WAIT1()  asm volatile("cp.async.wait_group 1;" ::: "memory")
#define CP_WAIT0()  asm volatile("cp.async.wait_group 0;" ::: "memory")

__device__ __forceinline__ void ldsm_x4(uint32_t& r0, uint32_t& r1,
                                        uint32_t& r2, uint32_t& r3,
                                        uint32_t addr) {
    asm volatile("ldmatrix.sync.aligned.m8n8.x4.shared.b16 {%0,%1,%2,%3}, [%4];"
                 : "=r"(r0), "=r"(r1), "=r"(r2), "=r"(r3) : "r"(addr));
}
__device__ __forceinline__ void mma16816(float* c, uint32_t a0, uint32_t a1,
                                         uint32_t a2, uint32_t a3,
                                         uint32_t b0, uint32_t b1) {
    asm volatile(
        "mma.sync.aligned.m16n8k16.row.col.f32.f16.f16.f32 "
        "{%0,%1,%2,%3}, {%4,%5,%6,%7}, {%8,%9}, {%0,%1,%2,%3};"
        : "+f"(c[0]), "+f"(c[1]), "+f"(c[2]), "+f"(c[3])
        : "r"(a0), "r"(a1), "r"(a2), "r"(a3), "r"(b0), "r"(b1));
}

// xor-swizzled smem offset for [row][granule16B] tiles, 512B rows (32 granules)
__device__ __forceinline__ uint32_t sw_off(uint32_t r, uint32_t g) {
    return r * 512u + ((((g & ~7u) | ((g ^ r) & 7u))) << 4);
}

// stage a [rows x 256] fp16 tile (granules = rows*32) into swizzled smem
__device__ __forceinline__ void stage_tile(uint32_t dst, const __half* gsrc,
                                           int granules, int tid) {
    const char* src = (const char*)gsrc;
    for (int g = tid; g < granules; g += 256) {
        uint32_t r = (uint32_t)g >> 5, gc = (uint32_t)g & 31;
        cpasync16(dst + sw_off(r, gc), src + (size_t)g * 16);
    }
}

// ---------------------------------------------------------------------------
// Prep: transpose embed [256][8192] -> embedT [8192][256]
// ---------------------------------------------------------------------------
__global__ void vq_transpose(const float* __restrict__ embed) {
    __shared__ float tile[32][33];
    int jB = blockIdx.x * 32, dB = blockIdx.y * 32;
    int tx = threadIdx.x, ty = threadIdx.y;
    #pragma unroll
    for (int r = ty; r < 32; r += 8)
        tile[r][tx] = embed[(size_t)(dB + r) * NE + jB + tx];
    __syncthreads();
    #pragma unroll
    for (int r = ty; r < 32; r += 8)
        g_embedT[(size_t)(jB + r) * DIM + dB + tx] = tile[tx][r];
}

// Prep: norms (identical op order to R1 kernel that measured rel_err 0.0)
__global__ void vq_norms() {
    int warp = threadIdx.x >> 5, lane = threadIdx.x & 31;
    int j = blockIdx.x * 8 + warp;
    const float4* row = (const float4*)(g_embedT + (size_t)j * DIM);
    float s = 0.f;
    #pragma unroll
    for (int i = lane; i < DIM / 4; i += 32) {
        float4 v = row[i];
        s += v.x * v.x + v.y * v.y + v.z * v.z + v.w * v.w;
    }
    #pragma unroll
    for (int o = 16; o; o >>= 1) s += __shfl_xor_sync(0xFFFFFFFFu, s, o);
    if (lane == 0) g_norms[j] = s;
}

// Prep: fp32 -> fp16
__global__ void vq_convert_x(const float* __restrict__ input) {
    int i = blockIdx.x * 256 + threadIdx.x;
    float4 v = ((const float4*)input)[i];
    __half2* dst = (__half2*)g_a_f16;
    dst[i * 2]     = __floats2half2_rn(v.x, v.y);
    dst[i * 2 + 1] = __floats2half2_rn(v.z, v.w);
}
__global__ void vq_convert_e() {
    int i = blockIdx.x * 256 + threadIdx.x;
    float4 v = ((const float4*)g_embedT)[i];
    __half2* dst = (__half2*)g_e_f16;
    dst[i * 2]     = __floats2half2_rn(v.x, v.y);
    dst[i * 2 + 1] = __floats2half2_rn(v.z, v.w);
}

// ---------------------------------------------------------------------------
// Main: mma.sync fp16 GEMM (fp32 accum) + fused per-row top candidates
// 8 warps as 4m x 2n, warp tile 32x64, CTA tile 128x128 per chunk.
// Each n-half warp owns candidate slots [nw*8, nw*8+8) — NO cross-warp clobber.
// ---------------------------------------------------------------------------
__global__ void __launch_bounds__(256, 1) vq_main() {
    extern __shared__ char smem[];
    const uint32_t sb = smem_u32(smem);
    const int tid = threadIdx.x, lane = tid & 31, warp = tid >> 5;
    const int mw = warp >> 1, nw = warp & 1;
    const int rowBase = blockIdx.x * MTILE;
    const int wr = mw * 32;

    // prologue staging: group0 = A + norms, group1 = B chunk0, group2 = B chunk1
    stage_tile(sb + OFF_A, g_a_f16 + (size_t)rowBase * DIM, 4096, tid);
    {
        const char* nsrc = (const char*)g_norms;
        for (int g = tid; g < 2048; g += 256)
            cpasync16(sb + OFF_NRM + (uint32_t)g * 16, nsrc + (size_t)g * 16);
    }
    CP_COMMIT();
    stage_tile(sb + OFF_B0, g_e_f16, 4096, tid);
    CP_COMMIT();
    stage_tile(sb + OFF_B1, g_e_f16 + (size_t)NTILE * DIM, 4096, tid);
    CP_COMMIT();
    CP_WAIT1();
    __syncthreads();

    // per-lane constants
    const int tig = lane & 3, gid = lane >> 2;
    const uint32_t aRow = (uint32_t)(wr + (lane & 15));
    const uint32_t ahalf = (uint32_t)(lane >> 4);
    const uint32_t bRow = (uint32_t)(nw * 64 + (lane & 7) + ((lane >> 4) << 3));
    const uint32_t bhalf = (uint32_t)((lane >> 3) & 1);

    // per-lane top-2 per owned row (4 rows), over this warp's n-half
    float cs[4][2];
    int   ci[4][2];
    #pragma unroll
    for (int rr = 0; rr < 4; rr++) {
        cs[rr][0] = __int_as_float(0x7F800000);
        cs[rr][1] = __int_as_float(0x7F800000);
        ci[rr][0] = 0; ci[rr][1] = 0;
    }
#define INS(rr, sc, jj) do {                                                   \
    float _s = (sc); int _j = (jj);                                            \
    if (_s < cs[rr][0]) { cs[rr][1] = cs[rr][0]; ci[rr][1] = ci[rr][0];        \
                          cs[rr][0] = _s;        ci[rr][0] = _j; }             \
    else if (_s < cs[rr][1]) { cs[rr][1] = _s; ci[rr][1] = _j; }               \
} while (0)

    for (int c = 0; c < CHUNKS; c++) {
        const uint32_t buf = sb + ((c & 1) ? OFF_B1 : OFF_B0);

        float acc[2][8][4];
        #pragma unroll
        for (int mt = 0; mt < 2; mt++)
            #pragma unroll
            for (int t = 0; t < 8; t++)
                #pragma unroll
                for (int q = 0; q < 4; q++) acc[mt][t][q] = 0.f;

        #pragma unroll
        for (int ki = 0; ki < KITERS; ki++) {
            const uint32_t gA = 2u * ki + ahalf;
            const uint32_t gB = 2u * ki + bhalf;
            uint32_t a0, a1, a2, a3, a4, a5, a6, a7;
            ldsm_x4(a0, a1, a2, a3, sb + OFF_A + sw_off(aRow, gA));
            ldsm_x4(a4, a5, a6, a7, sb + OFF_A + sw_off(aRow + 16, gA));
            uint32_t b[16];
            #pragma unroll
            for (int tp = 0; tp < 4; tp++)
                ldsm_x4(b[tp * 4], b[tp * 4 + 1], b[tp * 4 + 2], b[tp * 4 + 3],
                        buf + sw_off(bRow + tp * 16, gB));
            #pragma unroll
            for (int t = 0; t < 8; t++) {
                mma16816(acc[0][t], a0, a1, a2, a3, b[t * 2], b[t * 2 + 1]);
                mma16816(acc[1][t], a4, a5, a6, a7, b[t * 2], b[t * 2 + 1]);
            }
        }

        __syncthreads();                       // all warps done reading buf
        if (c + 2 < CHUNKS) {                  // refill same-parity buffer
            stage_tile(buf, g_e_f16 + (size_t)(c + 2) * NTILE * DIM, 4096, tid);
            CP_COMMIT();
        }

        // epilogue: score = ||e||^2 - 2*dot, update per-row top-2 (ascending j)
        const int cb = c * NTILE + nw * 64;
        const float* nrm = (const float*)(smem + OFF_NRM);
        #pragma unroll
        for (int t = 0; t < 8; t++) {
            int j0 = cb + t * 8 + 2 * tig;
            float n0 = nrm[j0], n1 = nrm[j0 + 1];
            #pragma unroll
            for (int mt = 0; mt < 2; mt++) {
                float s00 = fmaf(-2.f, acc[mt][t][0], n0);
                float s01 = fmaf(-2.f, acc[mt][t][1], n1);
                float s10 = fmaf(-2.f, acc[mt][t][2], n0);
                float s11 = fmaf(-2.f, acc[mt][t][3], n1);
                INS(mt * 2,     s00, j0); INS(mt * 2,     s01, j0 + 1);
                INS(mt * 2 + 1, s10, j0); INS(mt * 2 + 1, s11, j0 + 1);
            }
        }

        if (c + 2 < CHUNKS) { CP_WAIT1(); } else { CP_WAIT0(); }
        __syncthreads();
    }

    // write candidates: this warp's n-half owns slots [nw*8, nw*8+8)
    #pragma unroll
    for (int rr = 0; rr < 4; rr++) {
        int row = rowBase + wr + (rr >> 1) * 16 + gid + ((rr & 1) ? 8 : 0);
        float b = cs[rr][0];
        b = fminf(b, __shfl_xor_sync(0xFFFFFFFFu, b, 1));
        b = fminf(b, __shfl_xor_sync(0xFFFFFFFFu, b, 2));
        unsigned bal = __ballot_sync(0xFFFFFFFFu, cs[rr][1] <= b + MARGIN);
        bool flg = (bal >> (lane & 28)) & 0xFu;
        size_t base = (size_t)row * NCAND + nw * 8;
        g_cand[base + tig * 2 + 0] = ci[rr][0];
        g_cand[base + tig * 2 + 1] = ci[rr][1];
        if (flg && tig == 0) g_cand[base] = -1;   // flag this half
    }
#undef INS
}

// ---------------------------------------------------------------------------
// Refine: exact fp32 scores for 16 candidates, winner = min (first-index ties)
// If EITHER half flagged: full exact-scan fallback. One warp per row.
// ---------------------------------------------------------------------------
__global__ void __launch_bounds__(256) vq_refine(const float* __restrict__ input,
                                                 float* __restrict__ out) {
    const int wid = threadIdx.x >> 5, lane = threadIdx.x & 31;
    const int row = blockIdx.x * 8 + wid;

    const int c0 = g_cand[(size_t)row * NCAND];
    const int c8 = g_cand[(size_t)row * NCAND + 8];
    float bs = __int_as_float(0x7F800000);
    int   bj = 0x7FFFFFFF;

    if (c0 != -1 && c8 != -1) {
        float xr[8];
        const float4* xp = (const float4*)(input + (size_t)row * DIM + lane * 8);
        float4 x0 = xp[0], x1 = xp[1];
        xr[0] = x0.x; xr[1] = x0.y; xr[2] = x0.z; xr[3] = x0.w;
        xr[4] = x1.x; xr[5] = x1.y; xr[6] = x1.z; xr[7] = x1.w;
        #pragma unroll
        for (int t = 0; t < NCAND; t++) {
            int j = g_cand[(size_t)row * NCAND + t];
            const float4* ep = (const float4*)(g_embedT + (size_t)j * DIM + lane * 8);
            float4 e0 = ep[0], e1 = ep[1];
            float p = 0.f;
            p = fmaf(xr[0], e0.x, p); p = fmaf(xr[1], e0.y, p);
            p = fmaf(xr[2], e0.z, p); p = fmaf(xr[3], e0.w, p);
            p = fmaf(xr[4], e1.x, p); p = fmaf(xr[5], e1.y, p);
            p = fmaf(xr[6], e1.z, p); p = fmaf(xr[7], e1.w, p);
            #pragma unroll
            for (int o = 16; o; o >>= 1) p += __shfl_xor_sync(0xFFFFFFFFu, p, o);
            float s = fmaf(-2.f, p, g_norms[j]);
            if (s < bs || (s == bs && j < bj)) { bs = s; bj = j; }
        }
    } else {
        for (int j = lane; j < NE; j += 32) {
            const float* e = g_embedT + (size_t)j * DIM;
            const float* x = input + (size_t)row * DIM;
            float p = 0.f;
            for (int k = 0; k < DIM; k++) p = fmaf(x[k], e[k], p);
            float s = fmaf(-2.f, p, g_norms[j]);
            if (s < bs || (s == bs && j < bj)) { bs = s; bj = j; }
        }
        #pragma unroll
        for (int o = 16; o; o >>= 1) {
            float os = __shfl_xor_sync(0xFFFFFFFFu, bs, o);
            int   oj = __shfl_xor_sync(0xFFFFFFFFu, bj, o);
            if (os < bs || (os == bs && oj < bj)) { bs = os; bj = oj; }
        }
    }
    if (lane == 0) {
        g_idx[row] = bj;
        out[INDOFF + row] = (float)bj;
    }
}

// ---------------------------------------------------------------------------
// Output: gather + straight-through + per-block loss partial
// ---------------------------------------------------------------------------
__global__ void __launch_bounds__(256) vq_output(const float* __restrict__ input,
                                                 float* __restrict__ out) {
    __shared__ int sIdx[64];
    __shared__ float red[256];
    const int tid = threadIdx.x;
    const int rowBase = blockIdx.x * 64;
    if (tid < 64) sIdx[tid] = g_idx[rowBase + tid];
    __syncthreads();
    float lsum = 0.f;
    for (int r = 0; r < 64; r++) {
        int j = sIdx[r];
        float q = g_embedT[(size_t)j * DIM + tid];
        float x = input[(size_t)(rowBase + r) * DIM + tid];
        float d = q - x;
        out[(size_t)(rowBase + r) * DIM + tid] = x + d;   // straight-through
        lsum += d * d;
    }
    red[tid] = lsum;
    __syncthreads();
    #pragma unroll
    for (int s = 128; s; s >>= 1) {
        if (tid < s) red[tid] += red[tid + s];
        __syncthreads();
    }
    if (tid == 0) g_partial[blockIdx.x] = red[0];
}

__global__ void vq_loss_final(float* __restrict__ out) {
    __shared__ float red[512];
    red[threadIdx.x] = g_partial[threadIdx.x];
    __syncthreads();
    #pragma unroll
    for (int s = 256; s; s >>= 1) {
        if (threadIdx.x < s) red[threadIdx.x] += red[threadIdx.x + s];
        __syncthreads();
    }
    if (threadIdx.x == 0)
        out[LOSSOFF] = red[0] * (1.0f / (float)(N_ROWS * DIM));
}

// ---------------------------------------------------------------------------
extern "C" void kernel_launch(void* const* d_in, const int* in_sizes, int n_in,
                              void* d_out, int out_size) {
    const float* input = (const float*)d_in[0];   // [8,64,64,256]
    const float* embed = (const float*)d_in[1];   // [256,8192]
    float* out = (float*)d_out;

    cudaFuncSetAttribute(vq_main, cudaFuncAttributeMaxDynamicSharedMemorySize,
                         SMEM_BYTES);

    vq_transpose<<<dim3(NE / 32, DIM / 32), dim3(32, 8)>>>(embed);
    vq_norms<<<NE / 8, 256>>>();
    vq_convert_x<<<(N_ROWS * DIM / 4) / 256, 256>>>(input);
    vq_convert_e<<<(NE * DIM / 4) / 256, 256>>>();
    vq_main<<<N_ROWS / MTILE, 256, SMEM_BYTES>>>();
    vq_refine<<<N_ROWS / 8, 256>>>(input, out);
    vq_output<<<N_ROWS / 64, 256>>>(input, out);
    vq_loss_final<<<1, 512>>>(out);
}

// round 8
// speedup vs baseline: 1.1836x; 1.1836x over previous
#include <cuda_runtime.h>
#include <cuda_fp16.h>
#include <cstdint>

#define N_ROWS 32768
#define DIM    256
#define NE     8192

#define TM     128
#define TN     64
#define CH     (NE / TN)      // 128 chunks
#define AST    528            // As2 bytes per k row (128 dup-half2 + 16B pad)

#define NCAND  32
#define MARGIN 3.0f

#define INDOFF  (N_ROWS * DIM)         // 2097152
#define LOSSOFF (INDOFF + N_ROWS)      // 2129920

// smem layout (bytes)
#define OFF_A    0                      // 256 * 528 = 135168
#define OFF_B0   135168                 // 32 KB
#define OFF_B1   167936                 // 32 KB
#define OFF_BEST 200704                 // 128 * 8
#define SMEM_BYTES 201728

// Scratch (device globals: allocation-free per harness rules)
__device__ float  g_embedT[(size_t)NE * DIM];   // [8192][256] fp32 codebook rows
__device__ float  g_norms[NE];                  // ||e_j||^2
__device__ __half g_e16k[(size_t)DIM * NE];     // fp16 codebook, k-major [256][8192]
__device__ int    g_cand[(size_t)N_ROWS * NCAND];
__device__ int    g_flag[N_ROWS];
__device__ int    g_idx[N_ROWS];
__device__ float  g_partial[N_ROWS / 64];       // 512 loss partials

// ---------------------------------------------------------------------------
// helpers (base-target PTX only)
// ---------------------------------------------------------------------------
__device__ __forceinline__ uint32_t smem_u32(const void* p) {
    uint32_t a;
    asm("{ .reg .u64 t; cvta.to.shared.u64 t, %1; cvt.u32.u64 %0, t; }"
        : "=r"(a) : "l"(p));
    return a;
}
__device__ __forceinline__ void cpasync16(uint32_t dst, const void* src) {
    asm volatile("cp.async.cg.shared.global [%0], [%1], 16;"
                 :: "r"(dst), "l"(src) : "memory");
}
#define CP_COMMIT() asm volatile("cp.async.commit_group;" ::: "memory")
#define CP_WAIT1()  asm volatile("cp.async.wait_group 1;" ::: "memory")
#define CP_WAIT0()  asm volatile("cp.async.wait_group 0;" ::: "memory")

__device__ __forceinline__ __half2 as_h2(uint32_t u) {
    return *reinterpret_cast<const __half2*>(&u);
}

// ---------------------------------------------------------------------------
// Prep: transpose embed [256][8192] -> embedT [8192][256]  (for refine/output)
// ---------------------------------------------------------------------------
__global__ void vq_transpose(const float* __restrict__ embed) {
    __shared__ float tile[32][33];
    int jB = blockIdx.x * 32, dB = blockIdx.y * 32;
    int tx = threadIdx.x, ty = threadIdx.y;
    #pragma unroll
    for (int r = ty; r < 32; r += 8)
        tile[r][tx] = embed[(size_t)(dB + r) * NE + jB + tx];
    __syncthreads();
    #pragma unroll
    for (int r = ty; r < 32; r += 8)
        g_embedT[(size_t)(jB + r) * DIM + dB + tx] = tile[tx][r];
}

// Prep: norms (identical op order to R1 kernel that measured rel_err 0.0)
__global__ void vq_norms() {
    int warp = threadIdx.x >> 5, lane = threadIdx.x & 31;
    int j = blockIdx.x * 8 + warp;
    const float4* row = (const float4*)(g_embedT + (size_t)j * DIM);
    float s = 0.f;
    #pragma unroll
    for (int i = lane; i < DIM / 4; i += 32) {
        float4 v = row[i];
        s += v.x * v.x + v.y * v.y + v.z * v.z + v.w * v.w;
    }
    #pragma unroll
    for (int o = 16; o; o >>= 1) s += __shfl_xor_sync(0xFFFFFFFFu, s, o);
    if (lane == 0) g_norms[j] = s;
}

// Prep: fp32 embed [256][8192] -> fp16 same layout (k-major, natural col pairs)
__global__ void vq_convert_e() {
    int i = blockIdx.x * 256 + threadIdx.x;   // float4 index
    float4 v = ((const float4*)g_embedT)[0];  // dummy to keep symbol? no — use embed
    (void)v;
}
__global__ void vq_convert_e16(const float* __restrict__ embed) {
    int i = blockIdx.x * 256 + threadIdx.x;   // float4 index over 2M floats
    float4 v = ((const float4*)embed)[i];
    __half2* dst = (__half2*)g_e16k;
    dst[i * 2]     = __floats2half2_rn(v.x, v.y);
    dst[i * 2 + 1] = __floats2half2_rn(v.z, v.w);
}

// ---------------------------------------------------------------------------
// Main: packed-HFMA2 GEMM + fused per-row/thread top-2 + margin flag
// 256 threads (tx 0..15 = 4 cols, ty 0..15 = 8 rows). TM=128, TN=64, 128 chunks.
// ---------------------------------------------------------------------------
__global__ void __launch_bounds__(256, 1)
vq_main(const float* __restrict__ input) {
    extern __shared__ char smem[];
    const uint32_t sb = smem_u32(smem);
    unsigned long long* bestP = (unsigned long long*)(smem + OFF_BEST);

    const int tid = threadIdx.x;
    const int tx = tid & 15, ty = tid >> 4;
    const int rowBase = blockIdx.x * TM;

    if (tid < TM) bestP[tid] = 0xFFFFFFFFFFFFFFFFull;

    // ---- stage A: input rows -> As2[k][row] duplicated half2, AST stride ----
    {
        const float4* Ain = (const float4*)(input + (size_t)rowBase * DIM);
        #pragma unroll
        for (int it = 0; it < 32; it++) {
            int v = it * 256 + tid;           // 8192 float4 granules
            int r = v >> 6;                   // row 0..127
            int kb = (v & 63) << 2;           // k base
            float4 f = Ain[v];
            *(__half2*)(smem + OFF_A + (size_t)(kb + 0) * AST + r * 4) = __float2half2_rn(f.x);
            *(__half2*)(smem + OFF_A + (size_t)(kb + 1) * AST + r * 4) = __float2half2_rn(f.y);
            *(__half2*)(smem + OFF_A + (size_t)(kb + 2) * AST + r * 4) = __float2half2_rn(f.z);
            *(__half2*)(smem + OFF_A + (size_t)(kb + 3) * AST + r * 4) = __float2half2_rn(f.w);
        }
    }

    // ---- B producer: chunk c -> buffer (c&1). 2048 x 16B granules ----
    auto stageB = [&](uint32_t off, int c) {
        const char* base = (const char*)g_e16k + (size_t)c * (TN * 2);
        for (int v = tid; v < 2048; v += 256) {
            int k = v >> 3, g = v & 7;
            cpasync16(sb + off + (uint32_t)k * 128 + g * 16,
                      base + (size_t)k * (NE * 2) + g * 16);
        }
    };

    stageB(OFF_B0, 0);
    CP_COMMIT();

    // per-row top-2 (8 rows per thread), over this thread's 4 cols x 128 chunks
    float cs0[8], cs1[8];
    int   ci0[8], ci1[8];
    #pragma unroll
    for (int r = 0; r < 8; r++) {
        cs0[r] = __int_as_float(0x7F800000);
        cs1[r] = __int_as_float(0x7F800000);
        ci0[r] = 0; ci1[r] = 0;
    }
#define INS(r, sc, jj) do {                                                    \
    float _s = (sc); int _j = (jj);                                            \
    if (_s < cs0[r]) { cs1[r] = cs0[r]; ci1[r] = ci0[r];                       \
                       cs0[r] = _s;     ci0[r] = _j; }                         \
    else if (_s < cs1[r]) { cs1[r] = _s; ci1[r] = _j; }                        \
} while (0)

    for (int c = 0; c < CH; c++) {
        __syncthreads();                   // all warps done with buffer (c-1)&1
        if (c + 1 < CH) {
            stageB((c + 1) & 1 ? OFF_B1 : OFF_B0, c + 1);
            CP_COMMIT();
            CP_WAIT1();                    // chunk c's group complete
        } else {
            CP_WAIT0();
        }
        __syncthreads();                   // chunk c visible to all warps

        float4 nrm4 = ((const float4*)g_norms)[c * 16 + tx];
        const char* Bb = smem + ((c & 1) ? OFF_B1 : OFF_B0);
        const char* Ab = smem + OFF_A;

        float2 accf[8][2];
        #pragma unroll
        for (int r = 0; r < 8; r++) {
            accf[r][0] = make_float2(0.f, 0.f);
            accf[r][1] = make_float2(0.f, 0.f);
        }

        #pragma unroll
        for (int seg = 0; seg < 4; seg++) {
            __half2 acch[8][2];
            #pragma unroll
            for (int r = 0; r < 8; r++) {
                acch[r][0] = __float2half2_rn(0.f);
                acch[r][1] = __float2half2_rn(0.f);
            }
            #pragma unroll 8
            for (int kk = 0; kk < 64; kk++) {
                const int k = seg * 64 + kk;
                uint4 u0 = *(const uint4*)(Ab + (size_t)k * AST + ty * 32);
                uint4 u1 = *(const uint4*)(Ab + (size_t)k * AST + ty * 32 + 16);
                uint2 bu = *(const uint2*)(Bb + (size_t)k * 128 + tx * 8);
                __half2 b0 = as_h2(bu.x), b1 = as_h2(bu.y);
                __half2 a[8] = { as_h2(u0.x), as_h2(u0.y), as_h2(u0.z), as_h2(u0.w),
                                 as_h2(u1.x), as_h2(u1.y), as_h2(u1.z), as_h2(u1.w) };
                #pragma unroll
                for (int r = 0; r < 8; r++) {
                    acch[r][0] = __hfma2(a[r], b0, acch[r][0]);
                    acch[r][1] = __hfma2(a[r], b1, acch[r][1]);
                }
            }
            #pragma unroll
            for (int r = 0; r < 8; r++) {
                accf[r][0].x += __low2float(acch[r][0]);
                accf[r][0].y += __high2float(acch[r][0]);
                accf[r][1].x += __low2float(acch[r][1]);
                accf[r][1].y += __high2float(acch[r][1]);
            }
        }

        // epilogue: s = ||e||^2 - 2*dot, update per-row top-2 (ascending j)
        const int jb = c * TN + tx * 4;
        #pragma unroll
        for (int r = 0; r < 8; r++) {
            float s0 = fmaf(-2.f, accf[r][0].x, nrm4.x);
            float s1 = fmaf(-2.f, accf[r][0].y, nrm4.y);
            float s2 = fmaf(-2.f, accf[r][1].x, nrm4.z);
            float s3 = fmaf(-2.f, accf[r][1].y, nrm4.w);
            INS(r, s0, jb); INS(r, s1, jb + 1); INS(r, s2, jb + 2); INS(r, s3, jb + 3);
        }
    }
#undef INS

    // ---- combine row best across the 16 threads of each row ----
    #pragma unroll
    for (int r = 0; r < 8; r++) {
        unsigned u = __float_as_uint(cs0[r]);
        unsigned key = (u & 0x80000000u) ? ~u : (u | 0x80000000u);
        atomicMin(&bestP[ty * 8 + r],
                  ((unsigned long long)key << 32) | (unsigned)ci0[r]);
    }
    __syncthreads();

    // ---- margin flag + candidate write ----
    #pragma unroll
    for (int r = 0; r < 8; r++) {
        const int rowL = ty * 8 + r;
        unsigned bk = (unsigned)(bestP[rowL] >> 32);
        float bestf = __uint_as_float((bk & 0x80000000u) ? (bk & 0x7FFFFFFFu) : ~bk);
        bool f = (cs1[r] <= bestf + MARGIN);
        unsigned bal = __ballot_sync(0xFFFFFFFFu, f);
        unsigned bits = (bal >> ((ty & 1) * 16)) & 0xFFFFu;
        const int row = rowBase + rowL;
        if (tx == 0) g_flag[row] = (bits != 0u);
        g_cand[(size_t)row * NCAND + tx * 2 + 0] = ci0[r];
        g_cand[(size_t)row * NCAND + tx * 2 + 1] = ci1[r];
    }
}

// ---------------------------------------------------------------------------
// Refine: exact fp32 scores for 32 candidates (1 per lane), min w/ index ties;
// flagged rows: full exact scan. One warp per row.
// ---------------------------------------------------------------------------
__global__ void __launch_bounds__(256) vq_refine(const float* __restrict__ input,
                                                 float* __restrict__ out) {
    const int wid = threadIdx.x >> 5, lane = threadIdx.x & 31;
    const int row = blockIdx.x * 8 + wid;

    float bs;
    int   bj;

    if (!g_flag[row]) {
        const int j = g_cand[(size_t)row * NCAND + lane];
        const float4* xp = (const float4*)(input + (size_t)row * DIM);
        const float4* ep = (const float4*)(g_embedT + (size_t)j * DIM);
        float p0 = 0.f, p1 = 0.f, p2 = 0.f, p3 = 0.f;
        #pragma unroll 8
        for (int i = 0; i < 64; i += 4) {
            float4 x0 = xp[i],     e0 = ep[i];
            float4 x1 = xp[i + 1], e1 = ep[i + 1];
            float4 x2 = xp[i + 2], e2 = ep[i + 2];
            float4 x3 = xp[i + 3], e3 = ep[i + 3];
            p0 = fmaf(x0.x, e0.x, p0); p0 = fmaf(x0.y, e0.y, p0);
            p0 = fmaf(x0.z, e0.z, p0); p0 = fmaf(x0.w, e0.w, p0);
            p1 = fmaf(x1.x, e1.x, p1); p1 = fmaf(x1.y, e1.y, p1);
            p1 = fmaf(x1.z, e1.z, p1); p1 = fmaf(x1.w, e1.w, p1);
            p2 = fmaf(x2.x, e2.x, p2); p2 = fmaf(x2.y, e2.y, p2);
            p2 = fmaf(x2.z, e2.z, p2); p2 = fmaf(x2.w, e2.w, p2);
            p3 = fmaf(x3.x, e3.x, p3); p3 = fmaf(x3.y, e3.y, p3);
            p3 = fmaf(x3.z, e3.z, p3); p3 = fmaf(x3.w, e3.w, p3);
        }
        float p = (p0 + p1) + (p2 + p3);
        bs = fmaf(-2.f, p, g_norms[j]);
        bj = j;
    } else {
        bs = __int_as_float(0x7F800000);
        bj = 0x7FFFFFFF;
        for (int j = lane; j < NE; j += 32) {
            const float* e = g_embedT + (size_t)j * DIM;
            const float* x = input + (size_t)row * DIM;
            float p = 0.f;
            for (int k = 0; k < DIM; k++) p = fmaf(x[k], e[k], p);
            float s = fmaf(-2.f, p, g_norms[j]);
            if (s < bs || (s == bs && j < bj)) { bs = s; bj = j; }
        }
    }
    // warp argmin with first-index tie-break (also dedups repeated candidates)
    #pragma unroll
    for (int o = 16; o; o >>= 1) {
        float os = __shfl_xor_sync(0xFFFFFFFFu, bs, o);
        int   oj = __shfl_xor_sync(0xFFFFFFFFu, bj, o);
        if (os < bs || (os == bs && oj < bj)) { bs = os; bj = oj; }
    }
    if (lane == 0) {
        g_idx[row] = bj;
        out[INDOFF + row] = (float)bj;
    }
}

// ---------------------------------------------------------------------------
// Output: gather + straight-through + per-block loss partial
// ---------------------------------------------------------------------------
__global__ void __launch_bounds__(256) vq_output(const float* __restrict__ input,
                                                 float* __restrict__ out) {
    __shared__ int sIdx[64];
    __shared__ float red[256];
    const int tid = threadIdx.x;
    const int rowBase = blockIdx.x * 64;
    if (tid < 64) sIdx[tid] = g_idx[rowBase + tid];
    __syncthreads();
    float lsum = 0.f;
    for (int r = 0; r < 64; r++) {
        int j = sIdx[r];
        float q = g_embedT[(size_t)j * DIM + tid];
        float x = input[(size_t)(rowBase + r) * DIM + tid];
        float d = q - x;
        out[(size_t)(rowBase + r) * DIM + tid] = x + d;   // straight-through
        lsum += d * d;
    }
    red[tid] = lsum;
    __syncthreads();
    #pragma unroll
    for (int s = 128; s; s >>= 1) {
        if (tid < s) red[tid] += red[tid + s];
        __syncthreads();
    }
    if (tid == 0) g_partial[blockIdx.x] = red[0];
}

__global__ void vq_loss_final(float* __restrict__ out) {
    __shared__ float red[512];
    red[threadIdx.x] = g_partial[threadIdx.x];
    __syncthreads();
    #pragma unroll
    for (int s = 256; s; s >>= 1) {
        if (threadIdx.x < s) red[threadIdx.x] += red[threadIdx.x + s];
        __syncthreads();
    }
    if (threadIdx.x == 0)
        out[LOSSOFF] = red[0] * (1.0f / (float)(N_ROWS * DIM));
}

// ---------------------------------------------------------------------------
extern "C" void kernel_launch(void* const* d_in, const int* in_sizes, int n_in,
                              void* d_out, int out_size) {
    const float* input = (const float*)d_in[0];   // [8,64,64,256]
    const float* embed = (const float*)d_in[1];   // [256,8192]
    float* out = (float*)d_out;

    cudaFuncSetAttribute(vq_main, cudaFuncAttributeMaxDynamicSharedMemorySize,
                         SMEM_BYTES);

    vq_transpose<<<dim3(NE / 32, DIM / 32), dim3(32, 8)>>>(embed);
    vq_norms<<<NE / 8, 256>>>();
    vq_convert_e16<<<(NE * DIM / 4) / 256, 256>>>(embed);
    vq_main<<<N_ROWS / TM, 256, SMEM_BYTES>>>(input);
    vq_refine<<<N_ROWS / 8, 256>>>(input, out);
    vq_output<<<N_ROWS / 64, 256>>>(input, out);
    vq_loss_final<<<1, 512>>>(out);
}

// round 9
// speedup vs baseline: 2.8425x; 2.4015x over previous
#include <cuda_runtime.h>
#include <cstdint>

#define N_ROWS 32768
#define DIM    256
#define NE     8192
#define K4     (DIM / 4)      // 64 packed words per vector

#define TM     128
#define TN     128
#define CH     (NE / TN)      // 64 chunks

#define NCAND  32
#define MARGIN 4.0f

#define INDOFF  (N_ROWS * DIM)         // 2097152
#define LOSSOFF (INDOFF + N_ROWS)      // 2129920

// smem layout (bytes)
#define OFF_A    0                      // 64 k4 x 128 words = 32768
#define OFF_B0   32768                  // 32768
#define OFF_B1   65536                  // 32768
#define OFF_NRM  98304                  // 8192 floats = 32768
#define SMEM_BYTES 131072

// Scratch (device globals: allocation-free per harness rules)
__device__ float    g_embedT[(size_t)NE * DIM];  // [8192][256] fp32 codebook rows
__device__ float    g_norms[NE];                 // ||e_j||^2 exact fp32
__device__ unsigned g_a8[(size_t)N_ROWS * K4];   // int8-packed input, [row][k4]
__device__ unsigned g_e8[(size_t)K4 * NE];       // int8-packed codebook, [k4][j]
__device__ unsigned g_maxX, g_maxE;              // float-bits of max|.|
__device__ float    g_cscale;                    // -2/(sx*se)
__device__ int      g_cand[(size_t)N_ROWS * NCAND];
__device__ int      g_flag[N_ROWS];
__device__ int      g_idx[N_ROWS];
__device__ float    g_partial[N_ROWS / 64];      // 512 loss partials

// ---------------------------------------------------------------------------
// helpers (base-target PTX only)
// ---------------------------------------------------------------------------
__device__ __forceinline__ uint32_t smem_u32(const void* p) {
    uint32_t a;
    asm("{ .reg .u64 t; cvta.to.shared.u64 t, %1; cvt.u32.u64 %0, t; }"
        : "=r"(a) : "l"(p));
    return a;
}
__device__ __forceinline__ void cpasync16(uint32_t dst, const void* src) {
    asm volatile("cp.async.cg.shared.global [%0], [%1], 16;"
                 :: "r"(dst), "l"(src) : "memory");
}
#define CP_COMMIT() asm volatile("cp.async.commit_group;" ::: "memory")
#define CP_WAIT1()  asm volatile("cp.async.wait_group 1;" ::: "memory")
#define CP_WAIT0()  asm volatile("cp.async.wait_group 0;" ::: "memory")

__device__ __forceinline__ unsigned pack4(float a, float b, float c, float d,
                                          float s) {
    int q0 = __float2int_rn(a * s), q1 = __float2int_rn(b * s);
    int q2 = __float2int_rn(c * s), q3 = __float2int_rn(d * s);
    return (unsigned)(q0 & 255) | ((unsigned)(q1 & 255) << 8) |
           ((unsigned)(q2 & 255) << 16) | ((unsigned)(q3 & 255) << 24);
}

// ---------------------------------------------------------------------------
// Prep: transpose embed [256][8192] -> embedT [8192][256]
// ---------------------------------------------------------------------------
__global__ void vq_transpose(const float* __restrict__ embed) {
    __shared__ float tile[32][33];
    int jB = blockIdx.x * 32, dB = blockIdx.y * 32;
    int tx = threadIdx.x, ty = threadIdx.y;
    #pragma unroll
    for (int r = ty; r < 32; r += 8)
        tile[r][tx] = embed[(size_t)(dB + r) * NE + jB + tx];
    __syncthreads();
    #pragma unroll
    for (int r = ty; r < 32; r += 8)
        g_embedT[(size_t)(jB + r) * DIM + dB + tx] = tile[tx][r];
}

// Prep: norms (identical op order to R1 kernel that measured rel_err 0.0)
__global__ void vq_norms() {
    int warp = threadIdx.x >> 5, lane = threadIdx.x & 31;
    int j = blockIdx.x * 8 + warp;
    const float4* row = (const float4*)(g_embedT + (size_t)j * DIM);
    float s = 0.f;
    #pragma unroll
    for (int i = lane; i < DIM / 4; i += 32) {
        float4 v = row[i];
        s += v.x * v.x + v.y * v.y + v.z * v.z + v.w * v.w;
    }
    #pragma unroll
    for (int o = 16; o; o >>= 1) s += __shfl_xor_sync(0xFFFFFFFFu, s, o);
    if (lane == 0) g_norms[j] = s;
}

// Prep: scales (deterministic — max is order-independent)
__global__ void vq_zero_scales() { g_maxX = 0u; g_maxE = 0u; }

__global__ void vq_maxabs(const float* __restrict__ p, int which) {
    __shared__ float red[256];
    int i = blockIdx.x * 256 + threadIdx.x;
    float4 v = ((const float4*)p)[i];
    float m = fmaxf(fmaxf(fabsf(v.x), fabsf(v.y)), fmaxf(fabsf(v.z), fabsf(v.w)));
    red[threadIdx.x] = m;
    __syncthreads();
    #pragma unroll
    for (int s = 128; s; s >>= 1) {
        if (threadIdx.x < s) red[threadIdx.x] = fmaxf(red[threadIdx.x], red[threadIdx.x + s]);
        __syncthreads();
    }
    if (threadIdx.x == 0)
        atomicMax(which ? &g_maxE : &g_maxX, __float_as_uint(red[0]));
}

__global__ void vq_scales() {
    float sx = 126.5f / __uint_as_float(g_maxX);
    float se = 126.5f / __uint_as_float(g_maxE);
    g_cscale = -2.f / (sx * se);
    g_maxX = __float_as_uint(sx);   // reuse slots to carry scales
    g_maxE = __float_as_uint(se);
}

// Prep: pack input rows -> int8 words [row][k4]
__global__ void vq_pack_x(const float* __restrict__ input) {
    int i = blockIdx.x * 256 + threadIdx.x;        // word index == float4 index
    float s = __uint_as_float(g_maxX);
    float4 v = ((const float4*)input)[i];
    g_a8[i] = pack4(v.x, v.y, v.z, v.w, s);
}
// Prep: pack codebook (k-major) -> int8 words [k4][j]
__global__ void vq_pack_e(const float* __restrict__ embed) {
    int idx = blockIdx.x * 256 + threadIdx.x;      // 64*8192 words
    int k4 = idx >> 13, j = idx & (NE - 1);
    float s = __uint_as_float(g_maxE);
    const float* e = embed + (size_t)(k4 * 4) * NE + j;
    g_e8[idx] = pack4(e[0], e[NE], e[2 * NE], e[3 * NE], s);
}

// ---------------------------------------------------------------------------
// Main: dp4a int8 GEMM (exact int accum) + fused per-row/lane top-2 + flag
// 256 threads (tx 0..15 -> 8 cols, ty 0..15 -> 8 rows). TM=128, TN=128.
// ---------------------------------------------------------------------------
__global__ void __launch_bounds__(256, 1) vq_main() {
    extern __shared__ char smem[];
    const uint32_t sb = smem_u32(smem);
    unsigned* As = (unsigned*)(smem + OFF_A);

    const int tid = threadIdx.x;
    const int tx = tid & 15, ty = tid >> 4;
    const int lane = tid & 31;
    const int rowBase = blockIdx.x * TM;
    const float csc = g_cscale;

    // ---- stage A transposed: As[k4][row] ----
    #pragma unroll
    for (int it = 0; it < 8; it++) {
        int v = it * 256 + tid;               // 2048 uint4 = 128 rows x 16
        int r = v >> 4, kb = (v & 15) * 4;
        uint4 w = *(const uint4*)(g_a8 + (size_t)(rowBase + r) * K4 + kb);
        As[(kb + 0) * TM + r] = w.x;
        As[(kb + 1) * TM + r] = w.y;
        As[(kb + 2) * TM + r] = w.z;
        As[(kb + 3) * TM + r] = w.w;
    }

    // ---- cp.async: norms (32KB) + B chunk staging ----
    auto stageB = [&](uint32_t off, int c) {
        const char* base = (const char*)g_e8;
        for (int v = tid; v < 2048; v += 256) {
            int k4 = v >> 5, g = v & 31;      // 64 rows x 32 granules
            cpasync16(sb + off + (uint32_t)k4 * 512 + g * 16,
                      base + ((size_t)k4 * NE + (size_t)c * TN) * 4 + g * 16);
        }
    };
    {
        const char* nsrc = (const char*)g_norms;
        for (int g = tid; g < 2048; g += 256)
            cpasync16(sb + OFF_NRM + (uint32_t)g * 16, nsrc + (size_t)g * 16);
    }
    stageB(OFF_B0, 0);
    CP_COMMIT();

    // per-row top-2 (8 rows/thread) across this lane's 8 cols x 64 chunks
    float cs0[8], cs1[8];
    int   ci0[8], ci1[8];
    #pragma unroll
    for (int r = 0; r < 8; r++) {
        cs0[r] = __int_as_float(0x7F800000);
        cs1[r] = __int_as_float(0x7F800000);
        ci0[r] = 0; ci1[r] = 0;
    }
#define INS(r, sc, jj) do {                                                    \
    float _s = (sc); int _j = (jj);                                            \
    if (_s < cs0[r]) { cs1[r] = cs0[r]; ci1[r] = ci0[r];                       \
                       cs0[r] = _s;     ci0[r] = _j; }                         \
    else if (_s < cs1[r]) { cs1[r] = _s; ci1[r] = _j; }                        \
} while (0)

    for (int c = 0; c < CH; c++) {
        __syncthreads();                       // everyone done with this buffer
        if (c + 1 < CH) {
            stageB((c + 1) & 1 ? OFF_B1 : OFF_B0, c + 1);
            CP_COMMIT();
            CP_WAIT1();                        // chunk c's group complete
        } else {
            CP_WAIT0();
        }
        __syncthreads();

        const unsigned* Bb = (const unsigned*)(smem + ((c & 1) ? OFF_B1 : OFF_B0));

        int acc[8][8];
        #pragma unroll
        for (int i = 0; i < 8; i++)
            #pragma unroll
            for (int j = 0; j < 8; j++) acc[i][j] = 0;

        #pragma unroll 4
        for (int k4 = 0; k4 < K4; k4++) {
            uint4 a0 = *(const uint4*)(As + k4 * TM + ty * 8);
            uint4 a1 = *(const uint4*)(As + k4 * TM + ty * 8 + 4);
            uint4 b0 = *(const uint4*)(Bb + k4 * TN + tx * 8);
            uint4 b1 = *(const uint4*)(Bb + k4 * TN + tx * 8 + 4);
            unsigned a[8] = {a0.x, a0.y, a0.z, a0.w, a1.x, a1.y, a1.z, a1.w};
            unsigned b[8] = {b0.x, b0.y, b0.z, b0.w, b1.x, b1.y, b1.z, b1.w};
            #pragma unroll
            for (int i = 0; i < 8; i++)
                #pragma unroll
                for (int j = 0; j < 8; j++)
                    acc[i][j] = __dp4a((int)a[i], (int)b[j], acc[i][j]);
        }

        // epilogue: s = ||e||^2 + cscale*idot ; per-row top-2, ascending j
        const float* nrm = (const float*)(smem + OFF_NRM);
        const int jb = c * TN + tx * 8;
        #pragma unroll
        for (int j = 0; j < 8; j++) {
            float nj = nrm[jb + j];
            #pragma unroll
            for (int i = 0; i < 8; i++) {
                float s = fmaf(csc, (float)acc[i][j], nj);
                INS(i, s, jb + j);
            }
        }
    }
#undef INS

    // ---- per-row flag + candidate write (16 tx lanes per row = half-warp) ----
    #pragma unroll
    for (int r = 0; r < 8; r++) {
        float b = cs0[r];
        #pragma unroll
        for (int o = 1; o < 16; o <<= 1)
            b = fminf(b, __shfl_xor_sync(0xFFFFFFFFu, b, o));
        bool f = (cs1[r] <= b + MARGIN);
        unsigned bal = __ballot_sync(0xFFFFFFFFu, f);
        unsigned bits = (bal >> (lane & 16)) & 0xFFFFu;
        const int row = rowBase + ty * 8 + r;
        if (tx == 0) g_flag[row] = (bits != 0u);
        g_cand[(size_t)row * NCAND + tx * 2 + 0] = ci0[r];
        g_cand[(size_t)row * NCAND + tx * 2 + 1] = ci1[r];
    }
}

// ---------------------------------------------------------------------------
// Refine: exact fp32 scores for 32 candidates (1/lane); flagged rows: full
// vectorized exact scan. One warp per row; first-index tie-break.
// ---------------------------------------------------------------------------
__global__ void __launch_bounds__(256) vq_refine(const float* __restrict__ input,
                                                 float* __restrict__ out) {
    const int wid = threadIdx.x >> 5, lane = threadIdx.x & 31;
    const int row = blockIdx.x * 8 + wid;
    const float4* xp = (const float4*)(input + (size_t)row * DIM);

    float bs;
    int   bj;

    if (!g_flag[row]) {
        const int j = g_cand[(size_t)row * NCAND + lane];
        const float4* ep = (const float4*)(g_embedT + (size_t)j * DIM);
        float p0 = 0.f, p1 = 0.f, p2 = 0.f, p3 = 0.f;
        #pragma unroll 8
        for (int i = 0; i < 64; i += 4) {
            float4 x0 = xp[i],     e0 = ep[i];
            float4 x1 = xp[i + 1], e1 = ep[i + 1];
            float4 x2 = xp[i + 2], e2 = ep[i + 2];
            float4 x3 = xp[i + 3], e3 = ep[i + 3];
            p0 = fmaf(x0.x, e0.x, p0); p0 = fmaf(x0.y, e0.y, p0);
            p0 = fmaf(x0.z, e0.z, p0); p0 = fmaf(x0.w, e0.w, p0);
            p1 = fmaf(x1.x, e1.x, p1); p1 = fmaf(x1.y, e1.y, p1);
            p1 = fmaf(x1.z, e1.z, p1); p1 = fmaf(x1.w, e1.w, p1);
            p2 = fmaf(x2.x, e2.x, p2); p2 = fmaf(x2.y, e2.y, p2);
            p2 = fmaf(x2.z, e2.z, p2); p2 = fmaf(x2.w, e2.w, p2);
            p3 = fmaf(x3.x, e3.x, p3); p3 = fmaf(x3.y, e3.y, p3);
            p3 = fmaf(x3.z, e3.z, p3); p3 = fmaf(x3.w, e3.w, p3);
        }
        float p = (p0 + p1) + (p2 + p3);
        bs = fmaf(-2.f, p, g_norms[j]);
        bj = j;
    } else {
        bs = __int_as_float(0x7F800000);
        bj = 0x7FFFFFFF;
        for (int j = lane; j < NE; j += 32) {
            const float4* ep = (const float4*)(g_embedT + (size_t)j * DIM);
            float p0 = 0.f, p1 = 0.f, p2 = 0.f, p3 = 0.f;
            #pragma unroll 4
            for (int i = 0; i < 64; i += 4) {
                float4 x0 = xp[i],     e0 = ep[i];
                float4 x1 = xp[i + 1], e1 = ep[i + 1];
                float4 x2 = xp[i + 2], e2 = ep[i + 2];
                float4 x3 = xp[i + 3], e3 = ep[i + 3];
                p0 = fmaf(x0.x, e0.x, p0); p0 = fmaf(x0.y, e0.y, p0);
                p0 = fmaf(x0.z, e0.z, p0); p0 = fmaf(x0.w, e0.w, p0);
                p1 = fmaf(x1.x, e1.x, p1); p1 = fmaf(x1.y, e1.y, p1);
                p1 = fmaf(x1.z, e1.z, p1); p1 = fmaf(x1.w, e1.w, p1);
                p2 = fmaf(x2.x, e2.x, p2); p2 = fmaf(x2.y, e2.y, p2);
                p2 = fmaf(x2.z, e2.z, p2); p2 = fmaf(x2.w, e2.w, p2);
                p3 = fmaf(x3.x, e3.x, p3); p3 = fmaf(x3.y, e3.y, p3);
                p3 = fmaf(x3.z, e3.z, p3); p3 = fmaf(x3.w, e3.w, p3);
            }
            float p = (p0 + p1) + (p2 + p3);
            float s = fmaf(-2.f, p, g_norms[j]);
            if (s < bs || (s == bs && j < bj)) { bs = s; bj = j; }
        }
    }
    // warp argmin, first-index tie-break (dedups repeated candidates too)
    #pragma unroll
    for (int o = 16; o; o >>= 1) {
        float os = __shfl_xor_sync(0xFFFFFFFFu, bs, o);
        int   oj = __shfl_xor_sync(0xFFFFFFFFu, bj, o);
        if (os < bs || (os == bs && oj < bj)) { bs = os; bj = oj; }
    }
    if (lane == 0) {
        g_idx[row] = bj;
        out[INDOFF + row] = (float)bj;
    }
}

// ---------------------------------------------------------------------------
// Output: gather + straight-through + per-block loss partial
// ---------------------------------------------------------------------------
__global__ void __launch_bounds__(256) vq_output(const float* __restrict__ input,
                                                 float* __restrict__ out) {
    __shared__ int sIdx[64];
    __shared__ float red[256];
    const int tid = threadIdx.x;
    const int rowBase = blockIdx.x * 64;
    if (tid < 64) sIdx[tid] = g_idx[rowBase + tid];
    __syncthreads();
    float lsum = 0.f;
    for (int r = 0; r < 64; r++) {
        int j = sIdx[r];
        float q = g_embedT[(size_t)j * DIM + tid];
        float x = input[(size_t)(rowBase + r) * DIM + tid];
        float d = q - x;
        out[(size_t)(rowBase + r) * DIM + tid] = x + d;   // straight-through
        lsum += d * d;
    }
    red[tid] = lsum;
    __syncthreads();
    #pragma unroll
    for (int s = 128; s; s >>= 1) {
        if (tid < s) red[tid] += red[tid + s];
        __syncthreads();
    }
    if (tid == 0) g_partial[blockIdx.x] = red[0];
}

__global__ void vq_loss_final(float* __restrict__ out) {
    __shared__ float red[512];
    red[threadIdx.x] = g_partial[threadIdx.x];
    __syncthreads();
    #pragma unroll
    for (int s = 256; s; s >>= 1) {
        if (threadIdx.x < s) red[threadIdx.x] += red[threadIdx.x + s];
        __syncthreads();
    }
    if (threadIdx.x == 0)
        out[LOSSOFF] = red[0] * (1.0f / (float)(N_ROWS * DIM));
}

// ---------------------------------------------------------------------------
extern "C" void kernel_launch(void* const* d_in, const int* in_sizes, int n_in,
                              void* d_out, int out_size) {
    const float* input = (const float*)d_in[0];   // [8,64,64,256]
    const float* embed = (const float*)d_in[1];   // [256,8192]
    float* out = (float*)d_out;

    cudaFuncSetAttribute(vq_main, cudaFuncAttributeMaxDynamicSharedMemorySize,
                         SMEM_BYTES);

    vq_transpose<<<dim3(NE / 32, DIM / 32), dim3(32, 8)>>>(embed);
    vq_norms<<<NE / 8, 256>>>();
    vq_zero_scales<<<1, 1>>>();
    vq_maxabs<<<(N_ROWS * DIM / 4) / 256, 256>>>(input, 0);
    vq_maxabs<<<(NE * DIM / 4) / 256, 256>>>(embed, 1);
    vq_scales<<<1, 1>>>();
    vq_pack_x<<<(N_ROWS * K4) / 256, 256>>>(input);
    vq_pack_e<<<(K4 * NE) / 256, 256>>>(embed);
    vq_main<<<N_ROWS / TM, 256, SMEM_BYTES>>>();
    vq_refine<<<N_ROWS / 8, 256>>>(input, out);
    vq_output<<<N_ROWS / 64, 256>>>(input, out);
    vq_loss_final<<<1, 512>>>(out);
}